// round 7
// baseline (speedup 1.0000x reference)
#include <cuda_runtime.h>
#include <cstdint>

#define B_ 32
#define S_ 2048
#define D_ 64
// (1/sqrt(512)) * log2(e): exp(logit) == exp2(mma_result)
#define SCALE2_ (0.044194173824159216f * 1.4426950408889634f)

#define ST 68  // padded word stride for 64-wide smem tiles

__device__ __forceinline__ uint32_t f2tf32(float x) {
    uint32_t r;
    asm("cvt.rna.tf32.f32 %0, %1;" : "=r"(r) : "f"(x));
    return r;
}

// masked exp2: m!=0 -> 0, else ex2(x)
__device__ __forceinline__ float pexp2(int m, float x) {
    float r;
    asm("{\n\t.reg .pred p;\n\t"
        "setp.eq.s32 p, %1, 0;\n\t"
        "mov.f32 %0, 0f00000000;\n\t"
        "@p ex2.approx.f32 %0, %2;\n\t}"
        : "=f"(r) : "r"(m), "f"(x));
    return r;
}

__device__ __forceinline__ void mma8(float (&d)[4], const uint32_t (&a)[4],
                                     const uint32_t (&b)[2]) {
    asm volatile(
        "mma.sync.aligned.m16n8k8.row.col.f32.tf32.tf32.f32 "
        "{%0,%1,%2,%3}, {%4,%5,%6,%7}, {%8,%9}, {%0,%1,%2,%3};"
        : "+f"(d[0]), "+f"(d[1]), "+f"(d[2]), "+f"(d[3])
        : "r"(a[0]), "r"(a[1]), "r"(a[2]), "r"(a[3]), "r"(b[0]), "r"(b[1]));
}

__device__ __forceinline__ void cp16(uint32_t dst, const void* src) {
    asm volatile("cp.async.cg.shared.global [%0], [%1], 16;"
                 :: "r"(dst), "l"(src) : "memory");
}
#define CP_COMMIT() asm volatile("cp.async.commit_group;" ::: "memory")
#define CP_WAIT(n)  asm volatile("cp.async.wait_group %0;" :: "n"(n) : "memory")

__device__ __forceinline__ uint32_t smem_u32(const void* p) {
    uint32_t a;
    asm("{ .reg .u64 t; cvta.to.shared.u64 t, %1; cvt.u32.u64 %0, t; }"
        : "=r"(a) : "l"(p));
    return a;
}

// =============================================================================
// Fused attention: block = 64 q-rows x full S, k-tiles of 64, cp.async staged.
//   grid (32, 32), 128 threads (4 warps: 2 m x 2 n), 3 CTAs/SM.
//   smem 68.5KB: rs[64]pad | Qs 64x68 (tf32) | Ks 64x68 (raw f32) | Vs | P
// =============================================================================
__global__ __launch_bounds__(128, 3) void fused_attn_kernel(
        const float* __restrict__ q, const float* __restrict__ k,
        const float* __restrict__ v, const int* __restrict__ mask,
        float* __restrict__ attn, float* __restrict__ out) {
    extern __shared__ char sm[];
    float*    rs = (float*)sm;                   // [64] (+pad)
    uint32_t* Qs = (uint32_t*)(sm + 512);        // 64x68 tf32
    uint32_t* Ks = (uint32_t*)(sm + 17920);      // 64x68 raw fp32
    uint32_t* Vs = (uint32_t*)(sm + 35328);      // 64x68 raw fp32 (Vs[j][d])
    uint32_t* P  = (uint32_t*)(sm + 52736);      // 64x68 raw fp32 exp values

    const int tid = threadIdx.x, lane = tid & 31, wid = tid >> 5;
    const int wm = (wid & 1) * 32;   // warp m-base
    const int wn = wid >> 1;         // warp n-half (0/1)
    const int g = lane >> 2, e = lane & 3;
    const int b = blockIdx.y, i0 = blockIdx.x * 64;

    const uint32_t KsA = smem_u32(Ks), VsA = smem_u32(Vs);
    const float* kg = k + (size_t)b * S_ * D_;
    const float* vg = v + (size_t)b * S_ * D_;

    // cp.async dst offsets for this thread (8 chunks of 16B per tile)
    // chunk layout: row = idx>>4, c4 = (idx&15); dst = row*272B + c4*16B
    // prologue: issue K0 then V0
    {
        #pragma unroll
        for (int it = 0; it < 8; it++) {
            int idx = tid + it * 128;
            int row = idx >> 4, c4 = idx & 15;
            cp16(KsA + row * (ST * 4) + c4 * 16, kg + row * D_ + c4 * 4);
        }
        CP_COMMIT();
        #pragma unroll
        for (int it = 0; it < 8; it++) {
            int idx = tid + it * 128;
            int row = idx >> 4, c4 = idx & 15;
            cp16(VsA + row * (ST * 4) + c4 * 16, vg + row * D_ + c4 * 4);
        }
        CP_COMMIT();
    }

    if (tid < 64) rs[tid] = 0.f;

    // ---- stage Q once (scale*log2e folded, tf32 rna) ----
    const float* qg = q + ((size_t)b * S_ + i0) * D_;
    #pragma unroll
    for (int idx = tid; idx < 1024; idx += 128) {
        int row = idx >> 4, c4 = (idx & 15) << 2;
        float4 t = *(const float4*)(qg + row * D_ + c4);
        uint4 u = { f2tf32(t.x * SCALE2_), f2tf32(t.y * SCALE2_),
                    f2tf32(t.z * SCALE2_), f2tf32(t.w * SCALE2_) };
        *(uint4*)(Qs + row * ST + c4) = u;
    }

    float accpv[2][4][4];
    #pragma unroll
    for (int mi = 0; mi < 2; mi++)
        #pragma unroll
        for (int nj = 0; nj < 4; nj++)
            #pragma unroll
            for (int c = 0; c < 4; c++) accpv[mi][nj][c] = 0.f;

    #pragma unroll 1
    for (int ct = 0; ct < 32; ++ct) {
        const int j0 = ct * 64;

        // ---- prefetch mask fragment into registers (consumed post-QK) ----
        int2 mreg[2][2][4];
        #pragma unroll
        for (int mi = 0; mi < 2; mi++)
            #pragma unroll
            for (int h = 0; h < 2; h++) {
                int rl = wm + mi * 16 + h * 8 + g;
                const int* mrow =
                    mask + ((size_t)b * S_ + i0 + rl) * S_ + j0 + wn * 32;
                #pragma unroll
                for (int nj = 0; nj < 4; nj++)
                    mreg[mi][h][nj] = *(const int2*)(mrow + nj * 8 + 2 * e);
            }

        // ---- B1: K(ct) landed (allow V(ct) pending) ----
        CP_WAIT(1);
        __syncthreads();

        // ---- QK^T: warp tile 32x32 (Q tf32, K raw->truncated) ----
        float accq[2][4][4];
        #pragma unroll
        for (int mi = 0; mi < 2; mi++)
            #pragma unroll
            for (int nj = 0; nj < 4; nj++)
                #pragma unroll
                for (int c = 0; c < 4; c++) accq[mi][nj][c] = 0.f;

        #pragma unroll
        for (int ks = 0; ks < 8; ++ks) {
            uint32_t af[2][4];
            #pragma unroll
            for (int mi = 0; mi < 2; mi++) {
                int r0 = wm + mi * 16 + g;
                af[mi][0] = Qs[r0 * ST + ks * 8 + e];
                af[mi][1] = Qs[(r0 + 8) * ST + ks * 8 + e];
                af[mi][2] = Qs[r0 * ST + ks * 8 + 4 + e];
                af[mi][3] = Qs[(r0 + 8) * ST + ks * 8 + 4 + e];
            }
            #pragma unroll
            for (int nj = 0; nj < 4; nj++) {
                int col = wn * 32 + nj * 8 + g;
                uint32_t bf[2];
                bf[0] = Ks[col * ST + ks * 8 + e];
                bf[1] = Ks[col * ST + ks * 8 + 4 + e];
                mma8(accq[0][nj], af[0], bf);
                mma8(accq[1][nj], af[1], bf);
            }
        }

        // ---- merged epilogue: exp2 on fragments -> attn + P + rowsum ----
        #pragma unroll
        for (int mi = 0; mi < 2; mi++)
            #pragma unroll
            for (int h = 0; h < 2; h++) {
                int rl = wm + mi * 16 + h * 8 + g;
                float* arow =
                    attn + ((size_t)b * S_ + i0 + rl) * S_ + j0 + wn * 32;
                float s = 0.f;
                #pragma unroll
                for (int nj = 0; nj < 4; nj++) {
                    int2 m = mreg[mi][h][nj];
                    float e0 = pexp2(m.x, accq[mi][nj][h * 2 + 0]);
                    float e1 = pexp2(m.y, accq[mi][nj][h * 2 + 1]);
                    s += e0 + e1;
                    float2 w = { e0, e1 };
                    *(float2*)(arow + nj * 8 + 2 * e) = w;
                    *(float2*)((float*)(P + rl * ST + wn * 32) + nj * 8 + 2 * e) = w;
                }
                s += __shfl_xor_sync(0xffffffffu, s, 1);
                s += __shfl_xor_sync(0xffffffffu, s, 2);
                if (e == 0) atomicAdd(&rs[rl], s);
            }

        // ---- V(ct) must be fully landed before PV; fold into B2 ----
        CP_WAIT(0);
        __syncthreads();   // B2: P visible, V visible, Ks consumed

        // ---- prefetch K(ct+1) ----
        if (ct + 1 < 32) {
            const float* kn = kg + (size_t)(j0 + 64) * D_;
            #pragma unroll
            for (int it = 0; it < 8; it++) {
                int idx = tid + it * 128;
                int row = idx >> 4, c4 = idx & 15;
                cp16(KsA + row * (ST * 4) + c4 * 16, kn + row * D_ + c4 * 4);
            }
        }
        CP_COMMIT();

        // ---- PV: accpv += P @ V (both raw fp32 -> truncated tf32) ----
        #pragma unroll
        for (int ks = 0; ks < 8; ++ks) {
            uint32_t af[2][4];
            #pragma unroll
            for (int mi = 0; mi < 2; mi++) {
                int r0 = wm + mi * 16 + g;
                af[mi][0] = P[r0 * ST + ks * 8 + e];
                af[mi][1] = P[(r0 + 8) * ST + ks * 8 + e];
                af[mi][2] = P[r0 * ST + ks * 8 + 4 + e];
                af[mi][3] = P[(r0 + 8) * ST + ks * 8 + 4 + e];
            }
            #pragma unroll
            for (int nj = 0; nj < 4; nj++) {
                int d0 = wn * 32 + nj * 8 + g;
                uint32_t bf[2];
                bf[0] = Vs[(ks * 8 + e) * ST + d0];
                bf[1] = Vs[(ks * 8 + 4 + e) * ST + d0];
                mma8(accpv[0][nj], af[0], bf);
                mma8(accpv[1][nj], af[1], bf);
            }
        }
        __syncthreads();   // B3: P, Vs consumed

        // ---- prefetch V(ct+1) ----
        if (ct + 1 < 32) {
            const float* vn = vg + (size_t)(j0 + 64) * D_;
            #pragma unroll
            for (int it = 0; it < 8; it++) {
                int idx = tid + it * 128;
                int row = idx >> 4, c4 = idx & 15;
                cp16(VsA + row * (ST * 4) + c4 * 16, vn + row * D_ + c4 * 4);
            }
        }
        CP_COMMIT();
    }

    // ---- inverse rowsums ----
    __syncthreads();
    if (tid < 64) rs[tid] = __frcp_rn(rs[tid]);
    __syncthreads();

    // ---- out = accpv * inv ----
    #pragma unroll
    for (int mi = 0; mi < 2; mi++)
        #pragma unroll
        for (int h = 0; h < 2; h++) {
            int rl = wm + mi * 16 + h * 8 + g;
            float sc = rs[rl];
            float* orow = out + ((size_t)b * S_ + i0 + rl) * D_ + wn * 32;
            #pragma unroll
            for (int nj = 0; nj < 4; nj++) {
                float2 w = { accpv[mi][nj][h * 2 + 0] * sc,
                             accpv[mi][nj][h * 2 + 1] * sc };
                *(float2*)(orow + nj * 8 + 2 * e) = w;
            }
        }

    // ---- pass 2: normalize attn stripe in place ----
    float* ab = attn + ((size_t)b * S_ + i0) * S_;
    #pragma unroll 4
    for (int idx = tid; idx < 64 * 512; idx += 128) {
        int row = idx >> 9, c4 = (idx & 511) << 2;
        float sc = rs[row];
        float4* p = (float4*)(ab + (size_t)row * S_ + c4);
        float4 t = *p;
        t.x *= sc; t.y *= sc; t.z *= sc; t.w *= sc;
        *p = t;
    }
}

// =============================================================================
extern "C" void kernel_launch(void* const* d_in, const int* in_sizes, int n_in,
                              void* d_out, int out_size) {
    const float* q = (const float*)d_in[0];
    const float* k = (const float*)d_in[1];
    const float* v = (const float*)d_in[2];
    const int* mask = (const int*)d_in[3];

    float* out  = (float*)d_out;                 // [B,S,D]
    float* attn = out + (size_t)B_ * S_ * D_;    // [B,S,S]

    const int SMEM = 70144;  // 68.5 KB -> 3 CTAs/SM
    cudaFuncSetAttribute(fused_attn_kernel,
                         cudaFuncAttributeMaxDynamicSharedMemorySize, SMEM);

    dim3 grid(S_ / 64, B_);
    fused_attn_kernel<<<grid, 128, SMEM>>>(q, k, v, mask, attn, out);
}

// round 8
// speedup vs baseline: 1.2269x; 1.2269x over previous
#include <cuda_runtime.h>
#include <cstdint>

#define B_ 32
#define S_ 2048
#define D_ 64
// (1/sqrt(512)) * log2(e): exp(logit) == exp2(mma_result)
#define SCALE2_ (0.044194173824159216f * 1.4426950408889634f)

#define QST 68
#define KST 68
#define VST 72  // conflict-free for PV B-operand loads

// smem byte offsets
#define OFF_Q   0          // 128*68*4 = 34816
#define OFF_K0  34816      // 64*68*4 = 17408
#define OFF_K1  52224
#define OFF_V0  69632      // 64*72*4 = 18432
#define OFF_V1  88064
#define SMEM_TOTAL 106496  // 104 KB -> 2 CTAs/SM

__device__ __forceinline__ uint32_t f2tf32(float x) {
    uint32_t r;
    asm("cvt.rna.tf32.f32 %0, %1;" : "=r"(r) : "f"(x));
    return r;
}
__device__ __forceinline__ float pexp2(int m, float x) {
    float r;
    asm("{\n\t.reg .pred p;\n\t"
        "setp.eq.s32 p, %1, 0;\n\t"
        "mov.f32 %0, 0f00000000;\n\t"
        "@p ex2.approx.f32 %0, %2;\n\t}"
        : "=f"(r) : "r"(m), "f"(x));
    return r;
}
__device__ __forceinline__ void mma8(float (&d)[4], uint32_t a0, uint32_t a1,
                                     uint32_t a2, uint32_t a3,
                                     uint32_t b0, uint32_t b1) {
    asm volatile(
        "mma.sync.aligned.m16n8k8.row.col.f32.tf32.tf32.f32 "
        "{%0,%1,%2,%3}, {%4,%5,%6,%7}, {%8,%9}, {%0,%1,%2,%3};"
        : "+f"(d[0]), "+f"(d[1]), "+f"(d[2]), "+f"(d[3])
        : "r"(a0), "r"(a1), "r"(a2), "r"(a3), "r"(b0), "r"(b1));
}
__device__ __forceinline__ void cp16(uint32_t dst, const void* src) {
    asm volatile("cp.async.cg.shared.global [%0], [%1], 16;"
                 :: "r"(dst), "l"(src) : "memory");
}
#define CP_COMMIT() asm volatile("cp.async.commit_group;" ::: "memory")
#define CP_WAIT(n)  asm volatile("cp.async.wait_group %0;" :: "n"(n) : "memory")

__device__ __forceinline__ uint32_t smem_u32(const void* p) {
    uint32_t a;
    asm("{ .reg .u64 t; cvta.to.shared.u64 t, %1; cvt.u32.u64 %0, t; }"
        : "=r"(a) : "l"(p));
    return a;
}

// =============================================================================
// Fused attention, warp-private softmax/PV. CTA = 128 q-rows, 8 warps x 16 rows.
//   grid (16, 32), 256 threads, 2 CTAs/SM.
// =============================================================================
__global__ __launch_bounds__(256, 2) void fused_attn_kernel(
        const float* __restrict__ q, const float* __restrict__ k,
        const float* __restrict__ v, const int* __restrict__ mask,
        float* __restrict__ attn, float* __restrict__ out) {
    extern __shared__ char sm[];
    uint32_t* Qs = (uint32_t*)(sm + OFF_Q);
    const uint32_t smb = smem_u32(sm);

    const int tid = threadIdx.x, lane = tid & 31, wid = tid >> 5;
    const int wm = wid * 16;          // warp's 16 q-rows
    const int g = lane >> 2, e = lane & 3;
    const int b = blockIdx.y, i0 = blockIdx.x * 128;

    const float* kg = k + (size_t)b * S_ * D_;
    const float* vg = v + (size_t)b * S_ * D_;

    // per-thread cp.async chunk coords (4 chunks each for K and V)
    // idx = tid + it*256 ; row = idx>>4 ; c4 = idx&15
    // ---- prologue: issue K0,V0 -> buffers 0 ----
    #pragma unroll
    for (int it = 0; it < 4; it++) {
        int idx = tid + it * 256, row = idx >> 4, c4 = idx & 15;
        cp16(smb + OFF_K0 + row * (KST * 4) + c4 * 16, kg + row * D_ + c4 * 4);
    }
    #pragma unroll
    for (int it = 0; it < 4; it++) {
        int idx = tid + it * 256, row = idx >> 4, c4 = idx & 15;
        cp16(smb + OFF_V0 + row * (VST * 4) + c4 * 16, vg + row * D_ + c4 * 4);
    }
    CP_COMMIT();

    // ---- stage Q (scale*log2e folded, rna tf32) ----
    const float* qg = q + ((size_t)b * S_ + i0) * D_;
    #pragma unroll
    for (int it = 0; it < 8; it++) {
        int idx = tid + it * 256, row = idx >> 4, c4 = (idx & 15) << 2;
        float4 t = *(const float4*)(qg + row * D_ + c4);
        uint4 u = { f2tf32(t.x * SCALE2_), f2tf32(t.y * SCALE2_),
                    f2tf32(t.z * SCALE2_), f2tf32(t.w * SCALE2_) };
        *(uint4*)(Qs + row * QST + c4) = u;
    }

    // warp-private row bases (rows wm+g and wm+g+8)
    const size_t rowg  = ((size_t)b * S_ + i0 + wm + g) * S_;
    const size_t rowg8 = rowg + 8 * (size_t)S_;
    const int src0 = (lane & 28) | (e >> 1);  // g*4 + (e>>1)
    const int src1 = src0 + 2;
    const bool hi = (e & 1);

    float accpv[8][4];
    #pragma unroll
    for (int dj = 0; dj < 8; dj++)
        #pragma unroll
        for (int c = 0; c < 4; c++) accpv[dj][c] = 0.f;
    float rsum0 = 0.f, rsum1 = 0.f;

    #pragma unroll 1
    for (int ct = 0; ct < 32; ++ct) {
        const int j0 = ct * 64;
        const uint32_t kbuf = (ct & 1) ? OFF_K1 : OFF_K0;
        const uint32_t vbuf = (ct & 1) ? OFF_V1 : OFF_V0;
        uint32_t* Ks = (uint32_t*)(sm + kbuf);
        uint32_t* Vs = (uint32_t*)(sm + vbuf);

        __syncthreads();  // (A) prior-iter consumers of buf^1 done

        // issue prefetch of tile ct+1 into the other buffers
        if (ct + 1 < 32) {
            const uint32_t kb1 = (ct & 1) ? OFF_K0 : OFF_K1;
            const uint32_t vb1 = (ct & 1) ? OFF_V0 : OFF_V1;
            const float* kn = kg + (size_t)(j0 + 64) * D_;
            const float* vn = vg + (size_t)(j0 + 64) * D_;
            #pragma unroll
            for (int it = 0; it < 4; it++) {
                int idx = tid + it * 256, row = idx >> 4, c4 = idx & 15;
                cp16(smb + kb1 + row * (KST * 4) + c4 * 16, kn + row * D_ + c4 * 4);
            }
            #pragma unroll
            for (int it = 0; it < 4; it++) {
                int idx = tid + it * 256, row = idx >> 4, c4 = idx & 15;
                cp16(smb + vb1 + row * (VST * 4) + c4 * 16, vn + row * D_ + c4 * 4);
            }
        }
        CP_COMMIT();

        if (ct == 31) { CP_WAIT(0); } else { CP_WAIT(1); }

        // in-place rna rounding of this thread's own K/V chunks (tile ct)
        #pragma unroll
        for (int it = 0; it < 4; it++) {
            int idx = tid + it * 256, row = idx >> 4, c4 = (idx & 15) << 2;
            float4 tk = *(float4*)(Ks + row * KST + c4);
            uint4 uk = { f2tf32(tk.x), f2tf32(tk.y), f2tf32(tk.z), f2tf32(tk.w) };
            *(uint4*)(Ks + row * KST + c4) = uk;
            float4 tv = *(float4*)(Vs + row * VST + c4);
            uint4 uv = { f2tf32(tv.x), f2tf32(tv.y), f2tf32(tv.z), f2tf32(tv.w) };
            *(uint4*)(Vs + row * VST + c4) = uv;
        }
        __syncthreads();  // (B) tile ct published

        // ---- QK^T: warp tile 16x64 ----
        float accq[8][4];
        #pragma unroll
        for (int nj = 0; nj < 8; nj++)
            #pragma unroll
            for (int c = 0; c < 4; c++) accq[nj][c] = 0.f;

        #pragma unroll
        for (int ks = 0; ks < 8; ++ks) {
            uint32_t a0 = Qs[(wm + g) * QST + ks * 8 + e];
            uint32_t a1 = Qs[(wm + 8 + g) * QST + ks * 8 + e];
            uint32_t a2 = Qs[(wm + g) * QST + ks * 8 + 4 + e];
            uint32_t a3 = Qs[(wm + 8 + g) * QST + ks * 8 + 4 + e];
            #pragma unroll
            for (int nj = 0; nj < 8; nj++) {
                uint32_t b0 = Ks[(nj * 8 + g) * KST + ks * 8 + e];
                uint32_t b1 = Ks[(nj * 8 + g) * KST + ks * 8 + 4 + e];
                mma8(accq[nj], a0, a1, a2, a3, b0, b1);
            }
        }

        // ---- epilogue (warp-private): mask -> exp2 -> attn store + rowsum ----
        float sg = 0.f, sg8 = 0.f;
        #pragma unroll
        for (int nj = 0; nj < 8; nj++) {
            int co = j0 + nj * 8 + 2 * e;
            int2 mg = *(const int2*)(mask + rowg + co);
            int2 mh = *(const int2*)(mask + rowg8 + co);
            float e0 = pexp2(mg.x, accq[nj][0]);
            float e1 = pexp2(mg.y, accq[nj][1]);
            float e2 = pexp2(mh.x, accq[nj][2]);
            float e3 = pexp2(mh.y, accq[nj][3]);
            sg += e0 + e1;
            sg8 += e2 + e3;
            float2 w0 = { e0, e1 };
            float2 w1 = { e2, e3 };
            *(float2*)(attn + rowg + co) = w0;
            *(float2*)(attn + rowg8 + co) = w1;
            accq[nj][0] = e0; accq[nj][1] = e1;
            accq[nj][2] = e2; accq[nj][3] = e3;
        }
        // reduce over the 4 e-lanes (every lane ends with its rows' sums)
        sg  += __shfl_xor_sync(0xffffffffu, sg, 1);
        sg  += __shfl_xor_sync(0xffffffffu, sg, 2);
        sg8 += __shfl_xor_sync(0xffffffffu, sg8, 1);
        sg8 += __shfl_xor_sync(0xffffffffu, sg8, 2);
        rsum0 += sg;
        rsum1 += sg8;

        // ---- PV: C-frag -> A-frag via shfl, then accpv += P @ V ----
        #pragma unroll
        for (int nj = 0; nj < 8; nj++) {
            float p0 = accq[nj][0], p1 = accq[nj][1];
            float p2 = accq[nj][2], p3 = accq[nj][3];
            float t00 = __shfl_sync(0xffffffffu, p0, src0);
            float t01 = __shfl_sync(0xffffffffu, p1, src0);
            float t10 = __shfl_sync(0xffffffffu, p0, src1);
            float t11 = __shfl_sync(0xffffffffu, p1, src1);
            float t20 = __shfl_sync(0xffffffffu, p2, src0);
            float t21 = __shfl_sync(0xffffffffu, p3, src0);
            float t30 = __shfl_sync(0xffffffffu, p2, src1);
            float t31 = __shfl_sync(0xffffffffu, p3, src1);
            uint32_t a0 = f2tf32(hi ? t01 : t00);  // P[rg][e]
            uint32_t a1 = f2tf32(hi ? t21 : t20);  // P[rg8][e]
            uint32_t a2 = f2tf32(hi ? t11 : t10);  // P[rg][e+4]
            uint32_t a3 = f2tf32(hi ? t31 : t30);  // P[rg8][e+4]
            #pragma unroll
            for (int dj = 0; dj < 8; dj++) {
                uint32_t b0 = Vs[(nj * 8 + e) * VST + dj * 8 + g];
                uint32_t b1 = Vs[(nj * 8 + 4 + e) * VST + dj * 8 + g];
                mma8(accpv[dj], a0, a1, a2, a3, b0, b1);
            }
        }
    }

    // ---- warp-private finish: out = accpv * inv ----
    const float inv0 = __frcp_rn(rsum0);
    const float inv1 = __frcp_rn(rsum1);
    {
        float* o0 = out + ((size_t)b * S_ + i0 + wm + g) * D_;
        float* o1 = out + ((size_t)b * S_ + i0 + wm + 8 + g) * D_;
        #pragma unroll
        for (int dj = 0; dj < 8; dj++) {
            float2 w0 = { accpv[dj][0] * inv0, accpv[dj][1] * inv0 };
            float2 w1 = { accpv[dj][2] * inv1, accpv[dj][3] * inv1 };
            *(float2*)(o0 + dj * 8 + 2 * e) = w0;
            *(float2*)(o1 + dj * 8 + 2 * e) = w1;
        }
    }

    // ---- pass 2 (warp-private rows): normalize attn stripe in place ----
    {
        float* a0 = attn + rowg;
        float* a1 = attn + rowg8;
        #pragma unroll 4
        for (int kk = 0; kk < 128; kk++) {
            int c4 = (e + kk * 4) << 2;
            float4* p0 = (float4*)(a0 + c4);
            float4 t0 = *p0;
            t0.x *= inv0; t0.y *= inv0; t0.z *= inv0; t0.w *= inv0;
            *p0 = t0;
            float4* p1 = (float4*)(a1 + c4);
            float4 t1 = *p1;
            t1.x *= inv1; t1.y *= inv1; t1.z *= inv1; t1.w *= inv1;
            *p1 = t1;
        }
    }
}

// =============================================================================
extern "C" void kernel_launch(void* const* d_in, const int* in_sizes, int n_in,
                              void* d_out, int out_size) {
    const float* q = (const float*)d_in[0];
    const float* k = (const float*)d_in[1];
    const float* v = (const float*)d_in[2];
    const int* mask = (const int*)d_in[3];

    float* out  = (float*)d_out;                 // [B,S,D]
    float* attn = out + (size_t)B_ * S_ * D_;    // [B,S,S]

    cudaFuncSetAttribute(fused_attn_kernel,
                         cudaFuncAttributeMaxDynamicSharedMemorySize, SMEM_TOTAL);

    dim3 grid(S_ / 128, B_);
    fused_attn_kernel<<<grid, 256, SMEM_TOTAL>>>(q, k, v, mask, attn, out);
}

// round 9
// speedup vs baseline: 1.2575x; 1.0249x over previous
#include <cuda_runtime.h>
#include <cstdint>

#define B_ 32
#define S_ 2048
#define D_ 64
// (1/sqrt(512)) * log2(e): exp(logit) == exp2(mma_result)
#define SCALE2_ (0.044194173824159216f * 1.4426950408889634f)

#define QST 68
#define KST 68
#define VST 72  // conflict-free for PV B-operand loads

// smem byte offsets
#define OFF_Q   0          // 128*68*4 = 34816
#define OFF_K0  34816      // 64*68*4 = 17408
#define OFF_K1  52224
#define OFF_V0  69632      // 64*72*4 = 18432
#define OFF_V1  88064
#define SMEM_TOTAL 106496  // 104 KB -> 2 CTAs/SM

__device__ __forceinline__ uint32_t f2tf32(float x) {
    uint32_t r;
    asm("cvt.rna.tf32.f32 %0, %1;" : "=r"(r) : "f"(x));
    return r;
}
__device__ __forceinline__ float pexp2(int m, float x) {
    float r;
    asm("{\n\t.reg .pred p;\n\t"
        "setp.eq.s32 p, %1, 0;\n\t"
        "mov.f32 %0, 0f00000000;\n\t"
        "@p ex2.approx.f32 %0, %2;\n\t}"
        : "=f"(r) : "r"(m), "f"(x));
    return r;
}
__device__ __forceinline__ void mma8(float (&d)[4], uint32_t a0, uint32_t a1,
                                     uint32_t a2, uint32_t a3,
                                     uint32_t b0, uint32_t b1) {
    asm volatile(
        "mma.sync.aligned.m16n8k8.row.col.f32.tf32.tf32.f32 "
        "{%0,%1,%2,%3}, {%4,%5,%6,%7}, {%8,%9}, {%0,%1,%2,%3};"
        : "+f"(d[0]), "+f"(d[1]), "+f"(d[2]), "+f"(d[3])
        : "r"(a0), "r"(a1), "r"(a2), "r"(a3), "r"(b0), "r"(b1));
}
__device__ __forceinline__ void cp16(uint32_t dst, const void* src) {
    asm volatile("cp.async.cg.shared.global [%0], [%1], 16;"
                 :: "r"(dst), "l"(src) : "memory");
}
#define CP_COMMIT() asm volatile("cp.async.commit_group;" ::: "memory")
#define CP_WAIT(n)  asm volatile("cp.async.wait_group %0;" :: "n"(n) : "memory")

__device__ __forceinline__ uint32_t smem_u32(const void* p) {
    uint32_t a;
    asm("{ .reg .u64 t; cvta.to.shared.u64 t, %1; cvt.u32.u64 %0, t; }"
        : "=r"(a) : "l"(p));
    return a;
}

// =============================================================================
// Fused attention, warp-private softmax/PV, single barrier per k-tile.
//   CTA = 128 q-rows, 8 warps x 16 rows. grid (16, 32), 256 thr, 2 CTAs/SM.
// =============================================================================
__global__ __launch_bounds__(256, 2) void fused_attn_kernel(
        const float* __restrict__ q, const float* __restrict__ k,
        const float* __restrict__ v, const int* __restrict__ mask,
        float* __restrict__ attn, float* __restrict__ out) {
    extern __shared__ char sm[];
    uint32_t* Qs = (uint32_t*)(sm + OFF_Q);
    const uint32_t smb = smem_u32(sm);

    const int tid = threadIdx.x, lane = tid & 31, wid = tid >> 5;
    const int wm = wid * 16;          // warp's 16 q-rows
    const int g = lane >> 2, e = lane & 3;
    const int b = blockIdx.y, i0 = blockIdx.x * 128;

    const float* kg = k + (size_t)b * S_ * D_;
    const float* vg = v + (size_t)b * S_ * D_;

    // ---- prologue: issue K0,V0 -> buffers 0 (one group) ----
    #pragma unroll
    for (int it = 0; it < 4; it++) {
        int idx = tid + it * 256, row = idx >> 4, c4 = idx & 15;
        cp16(smb + OFF_K0 + row * (KST * 4) + c4 * 16, kg + row * D_ + c4 * 4);
    }
    #pragma unroll
    for (int it = 0; it < 4; it++) {
        int idx = tid + it * 256, row = idx >> 4, c4 = idx & 15;
        cp16(smb + OFF_V0 + row * (VST * 4) + c4 * 16, vg + row * D_ + c4 * 4);
    }
    CP_COMMIT();

    // ---- stage Q (scale*log2e folded, rna tf32); published by iter-0 barrier ----
    const float* qg = q + ((size_t)b * S_ + i0) * D_;
    #pragma unroll
    for (int it = 0; it < 8; it++) {
        int idx = tid + it * 256, row = idx >> 4, c4 = (idx & 15) << 2;
        float4 t = *(const float4*)(qg + row * D_ + c4);
        uint4 u = { f2tf32(t.x * SCALE2_), f2tf32(t.y * SCALE2_),
                    f2tf32(t.z * SCALE2_), f2tf32(t.w * SCALE2_) };
        *(uint4*)(Qs + row * QST + c4) = u;
    }

    // warp-private row bases (rows wm+g and wm+g+8)
    const size_t rowg  = ((size_t)b * S_ + i0 + wm + g) * S_;
    const size_t rowg8 = rowg + 8 * (size_t)S_;
    const int src0 = (lane & 28) | (e >> 1);  // g*4 + (e>>1)
    const int src1 = src0 + 2;
    const bool hi = (e & 1);

    float accpv[8][4];
    #pragma unroll
    for (int dj = 0; dj < 8; dj++)
        #pragma unroll
        for (int c = 0; c < 4; c++) accpv[dj][c] = 0.f;
    float rsum0 = 0.f, rsum1 = 0.f;

    #pragma unroll 1
    for (int ct = 0; ct < 32; ++ct) {
        const int j0 = ct * 64;
        uint32_t* Ks = (uint32_t*)(sm + ((ct & 1) ? OFF_K1 : OFF_K0));
        uint32_t* Vs = (uint32_t*)(sm + ((ct & 1) ? OFF_V1 : OFF_V0));

        // tile ct copies (issued last iter) done for THIS thread
        CP_WAIT(0);

        // round own chunks in place (exactly the chunks this thread copied)
        #pragma unroll
        for (int it = 0; it < 4; it++) {
            int idx = tid + it * 256, row = idx >> 4, c4 = (idx & 15) << 2;
            float4 tk = *(float4*)(Ks + row * KST + c4);
            uint4 uk = { f2tf32(tk.x), f2tf32(tk.y), f2tf32(tk.z), f2tf32(tk.w) };
            *(uint4*)(Ks + row * KST + c4) = uk;
            float4 tv = *(float4*)(Vs + row * VST + c4);
            uint4 uv = { f2tf32(tv.x), f2tf32(tv.y), f2tf32(tv.z), f2tf32(tv.w) };
            *(uint4*)(Vs + row * VST + c4) = uv;
        }

        // single barrier: publishes rounded tile ct (and Q on iter 0),
        // certifies all warps done with tile ct-1's buffers.
        __syncthreads();

        // issue prefetch of tile ct+1 into the other buffers
        if (ct + 1 < 32) {
            const uint32_t kb1 = (ct & 1) ? OFF_K0 : OFF_K1;
            const uint32_t vb1 = (ct & 1) ? OFF_V0 : OFF_V1;
            const float* kn = kg + (size_t)(j0 + 64) * D_;
            const float* vn = vg + (size_t)(j0 + 64) * D_;
            #pragma unroll
            for (int it = 0; it < 4; it++) {
                int idx = tid + it * 256, row = idx >> 4, c4 = idx & 15;
                cp16(smb + kb1 + row * (KST * 4) + c4 * 16, kn + row * D_ + c4 * 4);
            }
            #pragma unroll
            for (int it = 0; it < 4; it++) {
                int idx = tid + it * 256, row = idx >> 4, c4 = idx & 15;
                cp16(smb + vb1 + row * (VST * 4) + c4 * 16, vn + row * D_ + c4 * 4);
            }
            CP_COMMIT();
        }

        // ---- mask prefetch into registers (consumed after QK) ----
        int2 mg[8], mh[8];
        #pragma unroll
        for (int nj = 0; nj < 8; nj++) {
            int co = j0 + nj * 8 + 2 * e;
            mg[nj] = *(const int2*)(mask + rowg + co);
            mh[nj] = *(const int2*)(mask + rowg8 + co);
        }

        // ---- QK^T: warp tile 16x64 ----
        float accq[8][4];
        #pragma unroll
        for (int nj = 0; nj < 8; nj++)
            #pragma unroll
            for (int c = 0; c < 4; c++) accq[nj][c] = 0.f;

        #pragma unroll
        for (int ks = 0; ks < 8; ++ks) {
            uint32_t a0 = Qs[(wm + g) * QST + ks * 8 + e];
            uint32_t a1 = Qs[(wm + 8 + g) * QST + ks * 8 + e];
            uint32_t a2 = Qs[(wm + g) * QST + ks * 8 + 4 + e];
            uint32_t a3 = Qs[(wm + 8 + g) * QST + ks * 8 + 4 + e];
            #pragma unroll
            for (int nj = 0; nj < 8; nj++) {
                uint32_t b0 = Ks[(nj * 8 + g) * KST + ks * 8 + e];
                uint32_t b1 = Ks[(nj * 8 + g) * KST + ks * 8 + 4 + e];
                mma8(accq[nj], a0, a1, a2, a3, b0, b1);
            }
        }

        // ---- epilogue (warp-private): exp2 -> attn store + rowsum ----
        float sg = 0.f, sg8 = 0.f;
        #pragma unroll
        for (int nj = 0; nj < 8; nj++) {
            int co = j0 + nj * 8 + 2 * e;
            float e0 = pexp2(mg[nj].x, accq[nj][0]);
            float e1 = pexp2(mg[nj].y, accq[nj][1]);
            float e2 = pexp2(mh[nj].x, accq[nj][2]);
            float e3 = pexp2(mh[nj].y, accq[nj][3]);
            sg += e0 + e1;
            sg8 += e2 + e3;
            float2 w0 = { e0, e1 };
            float2 w1 = { e2, e3 };
            *(float2*)(attn + rowg + co) = w0;
            *(float2*)(attn + rowg8 + co) = w1;
            accq[nj][0] = e0; accq[nj][1] = e1;
            accq[nj][2] = e2; accq[nj][3] = e3;
        }
        sg  += __shfl_xor_sync(0xffffffffu, sg, 1);
        sg  += __shfl_xor_sync(0xffffffffu, sg, 2);
        sg8 += __shfl_xor_sync(0xffffffffu, sg8, 1);
        sg8 += __shfl_xor_sync(0xffffffffu, sg8, 2);
        rsum0 += sg;
        rsum1 += sg8;

        // ---- PV: C-frag -> A-frag via shfl, then accpv += P @ V ----
        #pragma unroll
        for (int nj = 0; nj < 8; nj++) {
            float p0 = accq[nj][0], p1 = accq[nj][1];
            float p2 = accq[nj][2], p3 = accq[nj][3];
            float t00 = __shfl_sync(0xffffffffu, p0, src0);
            float t01 = __shfl_sync(0xffffffffu, p1, src0);
            float t10 = __shfl_sync(0xffffffffu, p0, src1);
            float t11 = __shfl_sync(0xffffffffu, p1, src1);
            float t20 = __shfl_sync(0xffffffffu, p2, src0);
            float t21 = __shfl_sync(0xffffffffu, p3, src0);
            float t30 = __shfl_sync(0xffffffffu, p2, src1);
            float t31 = __shfl_sync(0xffffffffu, p3, src1);
            uint32_t a0 = f2tf32(hi ? t01 : t00);  // P[rg][e]
            uint32_t a1 = f2tf32(hi ? t21 : t20);  // P[rg8][e]
            uint32_t a2 = f2tf32(hi ? t11 : t10);  // P[rg][e+4]
            uint32_t a3 = f2tf32(hi ? t31 : t30);  // P[rg8][e+4]
            #pragma unroll
            for (int dj = 0; dj < 8; dj++) {
                uint32_t b0 = Vs[(nj * 8 + e) * VST + dj * 8 + g];
                uint32_t b1 = Vs[(nj * 8 + 4 + e) * VST + dj * 8 + g];
                mma8(accpv[dj], a0, a1, a2, a3, b0, b1);
            }
        }
    }

    // ---- warp-private finish: out = accpv * inv ----
    const float inv0 = __frcp_rn(rsum0);
    const float inv1 = __frcp_rn(rsum1);
    {
        float* o0 = out + ((size_t)b * S_ + i0 + wm + g) * D_;
        float* o1 = out + ((size_t)b * S_ + i0 + wm + 8 + g) * D_;
        #pragma unroll
        for (int dj = 0; dj < 8; dj++) {
            float2 w0 = { accpv[dj][0] * inv0, accpv[dj][1] * inv0 };
            float2 w1 = { accpv[dj][2] * inv1, accpv[dj][3] * inv1 };
            *(float2*)(o0 + dj * 8 + 2 * e) = w0;
            *(float2*)(o1 + dj * 8 + 2 * e) = w1;
        }
    }

    // ---- pass 2 (warp-private rows): normalize attn stripe in place ----
    {
        float* a0 = attn + rowg;
        float* a1 = attn + rowg8;
        #pragma unroll 4
        for (int kk = 0; kk < 128; kk++) {
            int c4 = (e + kk * 4) << 2;
            float4* p0 = (float4*)(a0 + c4);
            float4 t0 = *p0;
            t0.x *= inv0; t0.y *= inv0; t0.z *= inv0; t0.w *= inv0;
            *p0 = t0;
            float4* p1 = (float4*)(a1 + c4);
            float4 t1 = *p1;
            t1.x *= inv1; t1.y *= inv1; t1.z *= inv1; t1.w *= inv1;
            *p1 = t1;
        }
    }
}

// =============================================================================
extern "C" void kernel_launch(void* const* d_in, const int* in_sizes, int n_in,
                              void* d_out, int out_size) {
    const float* q = (const float*)d_in[0];
    const float* k = (const float*)d_in[1];
    const float* v = (const float*)d_in[2];
    const int* mask = (const int*)d_in[3];

    float* out  = (float*)d_out;                 // [B,S,D]
    float* attn = out + (size_t)B_ * S_ * D_;    // [B,S,S]

    cudaFuncSetAttribute(fused_attn_kernel,
                         cudaFuncAttributeMaxDynamicSharedMemorySize, SMEM_TOTAL);

    dim3 grid(S_ / 128, B_);
    fused_attn_kernel<<<grid, 256, SMEM_TOTAL>>>(q, k, v, mask, attn, out);
}